// round 1
// baseline (speedup 1.0000x reference)
#include <cuda_runtime.h>

// PositionalEncoding: out[b,t,i] = x[b,t,i] + P[t,i]
//   P[2f,   i] = sin(f / 10000^(2i/F))
//   P[2f+1, i] = cos(f / 10000^(2i/F))
// x: [32, 2048, 1024] fp32.  Memory-bound; P computed once per (t,i) and
// reused across the 32-batch loop inside each thread.

#define PE_T 2048
#define PE_F 1024
#define PE_B 32

__global__ __launch_bounds__(256, 4)
void pe_add_kernel(const float* __restrict__ x, float* __restrict__ out) {
    const int t = blockIdx.x;          // row 0..2047
    const int c = threadIdx.x;         // float4 column 0..255
    const float f = (float)(t >> 1);
    const bool is_sin = (t & 1) == 0;

    float pv[4];
#pragma unroll
    for (int k = 0; k < 4; k++) {
        const int i = c * 4 + k;
        const float e = (float)i * (1.0f / 512.0f);   // 2*i/F, exact in fp32
        const float den = powf(10000.0f, e);
        const float ang = f / den;
        pv[k] = is_sin ? sinf(ang) : cosf(ang);
    }
    const float4 p = make_float4(pv[0], pv[1], pv[2], pv[3]);

    const float4* __restrict__ x4 = (const float4*)x;
    float4* __restrict__ o4 = (float4*)out;
    const size_t row_stride4 = (size_t)PE_T * (PE_F / 4);   // float4 per batch slice
    const size_t base = (size_t)t * (PE_F / 4) + (size_t)c;

#pragma unroll 8
    for (int b = 0; b < PE_B; b++) {
        const size_t idx = base + (size_t)b * row_stride4;
        float4 v = x4[idx];
        v.x += p.x;
        v.y += p.y;
        v.z += p.z;
        v.w += p.w;
        o4[idx] = v;
    }
}

extern "C" void kernel_launch(void* const* d_in, const int* in_sizes, int n_in,
                              void* d_out, int out_size) {
    const float* x = (const float*)d_in[0];
    float* out = (float*)d_out;
    pe_add_kernel<<<PE_T, 256>>>(x, out);
}